// round 3
// baseline (speedup 1.0000x reference)
#include <cuda_runtime.h>
#include <math.h>

#define B_   64
#define S_   4096
#define DEC_ 512
#define ENC_ 256

// Scratch (allocation-free rule: __device__ globals)
__device__ float g_dpe[B_ * ENC_];      // decoder_proj + bd + be, per batch
__device__ float g_scores[B_ * S_];     // pre-softmax scores

// ---------------------------------------------------------------------------
// Kernel 1: dpe[b,f] = sum_d dh[b,d]*Wd[d,f] + bd[f] + be[f]
// ---------------------------------------------------------------------------
__global__ void k_decproj(const float* __restrict__ dh, const float* __restrict__ Wd,
                          const float* __restrict__ bd, const float* __restrict__ be) {
    int b = blockIdx.x;
    int f = threadIdx.x;                 // 256 threads
    __shared__ float sdh[DEC_];
    for (int d = f; d < DEC_; d += ENC_) sdh[d] = dh[b * DEC_ + d];
    __syncthreads();
    float acc = bd[f] + be[f];
#pragma unroll 8
    for (int d = 0; d < DEC_; ++d) acc += sdh[d] * Wd[d * ENC_ + f];
    g_dpe[b * ENC_ + f] = acc;
}

// ---------------------------------------------------------------------------
// Kernel 2: fused GEMM + tanh + Wa-dot -> scores
//   CTA tile: 128 rows (one batch slice) x 256 cols (all ENC), BK=8
//   256 threads = 16x16; thread micro-tile 8 rows x 8 col-pairs (f32x2)
// ---------------------------------------------------------------------------
__device__ __forceinline__ void cp16(void* dst, const void* src) {
    unsigned d = (unsigned)__cvta_generic_to_shared(dst);
    asm volatile("cp.async.cg.shared.global [%0], [%1], 16;\n" :: "r"(d), "l"(src));
}
#define CP_COMMIT() asm volatile("cp.async.commit_group;\n" ::: "memory")
#define CP_WAIT1()  asm volatile("cp.async.wait_group 1;\n" ::: "memory")

__global__ __launch_bounds__(256, 1)
void k_scores(const float* __restrict__ enc, const float* __restrict__ We,
              const float* __restrict__ Wa) {
    __shared__ __align__(16) float As[2][128][8];     // 8 KB
    __shared__ __align__(16) float Bs[2][8][256];     // 16 KB
    __shared__ float red[128][17];                    // 8.5 KB, padded
    __shared__ float sdpe[256];
    __shared__ float swa[256];

    const int tid = threadIdx.x;
    const int tx = tid & 15, ty = tid >> 4;
    const int row0 = blockIdx.x * 128;                // global (b*S + s) row
    const int b = row0 >> 12;                         // S = 4096 rows per batch

    sdpe[tid] = g_dpe[b * 256 + tid];
    swa[tid]  = Wa[tid];

    // A-tile loader mapping: 1 float4 per thread per K-tile
    const int arow = tid >> 1, aseg = (tid & 1) * 4;
    const float* agp = enc + (size_t)(row0 + arow) * 256 + aseg;

    unsigned long long acc[8][8];
#pragma unroll
    for (int i = 0; i < 8; ++i)
#pragma unroll
        for (int j = 0; j < 8; ++j) acc[i][j] = 0ull;

    // prologue: K-tile 0
    {
        cp16(&As[0][arow][aseg], agp);
        int i0 = tid, i1 = tid + 256;
        cp16(&Bs[0][i0 >> 6][(i0 & 63) * 4], We + (i0 >> 6) * 256 + (i0 & 63) * 4);
        cp16(&Bs[0][i1 >> 6][(i1 & 63) * 4], We + (i1 >> 6) * 256 + (i1 & 63) * 4);
        CP_COMMIT();
    }

    for (int t = 0; t < 32; ++t) {
        const int buf = t & 1;
        if (t + 1 < 32) {                              // prefetch next K-tile
            const int kt = (t + 1) * 8, nb = buf ^ 1;
            cp16(&As[nb][arow][aseg], agp + kt);
            int i0 = tid, i1 = tid + 256;
            int kr0 = i0 >> 6, c0 = (i0 & 63) * 4;
            int kr1 = i1 >> 6, c1 = (i1 & 63) * 4;
            cp16(&Bs[nb][kr0][c0], We + (kt + kr0) * 256 + c0);
            cp16(&Bs[nb][kr1][c1], We + (kt + kr1) * 256 + c1);
        }
        CP_COMMIT();
        CP_WAIT1();                                    // tile t resident
        __syncthreads();

#pragma unroll
        for (int k = 0; k < 8; ++k) {
            unsigned long long ap[8], bp[8];
#pragma unroll
            for (int i = 0; i < 8; ++i) {
                float av = As[buf][ty * 8 + i][k];     // 2 addrs/warp -> broadcast
                asm("mov.b64 %0, {%1, %1};" : "=l"(ap[i]) : "f"(av));
            }
#pragma unroll
            for (int j = 0; j < 8; ++j)                // cols 2*tx + 32*j: conflict-free
                bp[j] = *(const unsigned long long*)&Bs[buf][k][2 * tx + 32 * j];
#pragma unroll
            for (int i = 0; i < 8; ++i)
#pragma unroll
                for (int j = 0; j < 8; ++j)
                    asm("fma.rn.f32x2 %0, %1, %2, %0;"
                        : "+l"(acc[i][j]) : "l"(ap[i]), "l"(bp[j]));
        }
        __syncthreads();                               // protect buf reuse at t+2
    }

    // Epilogue: scores partials = sum_f Wa[f] * tanh(dpe[f] + ep)
#pragma unroll
    for (int i = 0; i < 8; ++i) {
        float si = 0.f;
#pragma unroll
        for (int j = 0; j < 8; ++j) {
            float lo, hi;
            asm("mov.b64 {%0, %1}, %2;" : "=f"(lo), "=f"(hi) : "l"(acc[i][j]));
            const int c = 2 * tx + 32 * j;
            si += swa[c]     * tanhf(sdpe[c]     + lo);
            si += swa[c + 1] * tanhf(sdpe[c + 1] + hi);
        }
        red[ty * 8 + i][tx] = si;
    }
    __syncthreads();
    if (tid < 128) {
        float s = 0.f;
#pragma unroll
        for (int x = 0; x < 16; ++x) s += red[tid][x];
        g_scores[row0 + tid] = s;
    }
}

// ---------------------------------------------------------------------------
// Kernel 3: masked softmax over S per batch -> attn (output region)
// ---------------------------------------------------------------------------
__global__ void k_softmax(const int* __restrict__ mask, float* __restrict__ attn) {
    const int b = blockIdx.x, t = threadIdx.x;         // 1024 threads
    const float* sc = g_scores + b * S_;
    const int*   mk = mask + b * S_;
    float v[4], mx = -INFINITY;
#pragma unroll
    for (int i = 0; i < 4; ++i) {
        int s = t + i * 1024;
        float x = sc[s];
        if (mk[s] == 0) x = -1e10f;
        v[i] = x;
        mx = fmaxf(mx, x);
    }
    __shared__ float rb[32];
    for (int o = 16; o; o >>= 1) mx = fmaxf(mx, __shfl_xor_sync(~0u, mx, o));
    if ((t & 31) == 0) rb[t >> 5] = mx;
    __syncthreads();
    if (t < 32) {
        float m2 = rb[t];
        for (int o = 16; o; o >>= 1) m2 = fmaxf(m2, __shfl_xor_sync(~0u, m2, o));
        rb[t] = m2;
    }
    __syncthreads();
    mx = rb[0];
    __syncthreads();
    float e[4], tot = 0.f;
#pragma unroll
    for (int i = 0; i < 4; ++i) { e[i] = expf(v[i] - mx); tot += e[i]; }
    for (int o = 16; o; o >>= 1) tot += __shfl_xor_sync(~0u, tot, o);
    if ((t & 31) == 0) rb[t >> 5] = tot;
    __syncthreads();
    if (t < 32) {
        float s2 = rb[t];
        for (int o = 16; o; o >>= 1) s2 += __shfl_xor_sync(~0u, s2, o);
        rb[t] = s2;
    }
    __syncthreads();
    const float inv = 1.f / rb[0];
#pragma unroll
    for (int i = 0; i < 4; ++i) attn[b * S_ + t + i * 1024] = e[i] * inv;
}

// ---------------------------------------------------------------------------
// Kernel 4: context[b,e] = sum_s attn[b,s] * enc[b,s,e]  (float4 vectorized)
// ---------------------------------------------------------------------------
__global__ void k_context(const float* __restrict__ enc, const float* __restrict__ attn,
                          float* __restrict__ ctx) {
    const int b = blockIdx.x, t = threadIdx.x;         // 1024 threads
    const int c4 = t & 63, sg = t >> 6;                // 64 float4 cols x 16 s-phases
    const float4* e4 = (const float4*)enc + (size_t)b * S_ * 64;
    const float* at = attn + b * S_;
    float4 acc = make_float4(0.f, 0.f, 0.f, 0.f);
#pragma unroll 4
    for (int s = sg; s < S_; s += 16) {
        float a = at[s];
        float4 e = e4[(size_t)s * 64 + c4];
        acc.x += a * e.x; acc.y += a * e.y; acc.z += a * e.z; acc.w += a * e.w;
    }
    __shared__ float4 sr[16][64];                      // 16 KB
    sr[sg][c4] = acc;
    __syncthreads();
    if (t < 64) {
        float4 r = sr[0][t];
#pragma unroll
        for (int g = 1; g < 16; ++g) {
            float4 q = sr[g][t];
            r.x += q.x; r.y += q.y; r.z += q.z; r.w += q.w;
        }
        ((float4*)ctx)[b * 64 + t] = r;
    }
}

// ---------------------------------------------------------------------------
// Launch
// ---------------------------------------------------------------------------
extern "C" void kernel_launch(void* const* d_in, const int* in_sizes, int n_in,
                              void* d_out, int out_size) {
    const float* dh   = (const float*)d_in[0];  // decoder_hidden [64,1,512]
    const float* enc  = (const float*)d_in[1];  // encoder_outputs [64,4096,256]
    const int*   mask = (const int*)  d_in[2];  // [64,4096]
    const float* Wd   = (const float*)d_in[3];  // [512,256]
    const float* bd   = (const float*)d_in[4];  // [256]
    const float* We   = (const float*)d_in[5];  // [256,256]
    const float* be   = (const float*)d_in[6];  // [256]
    const float* Wa   = (const float*)d_in[7];  // [256]
    // d_in[8] = ba: uniform additive shift on scores -> cancels in softmax.

    float* out  = (float*)d_out;
    float* ctx  = out;                 // context [64,1,256] first (return order)
    float* attn = out + B_ * ENC_;     // attn [64,4096] second

    k_decproj<<<B_, ENC_>>>(dh, Wd, bd, be);
    k_scores<<<(B_ * S_) / 128, 256>>>(enc, We, Wa);
    k_softmax<<<B_, 1024>>>(mask, attn);
    k_context<<<B_, 1024>>>(enc, attn, ctx);
}

// round 5
// speedup vs baseline: 2.0555x; 2.0555x over previous
#include <cuda_runtime.h>
#include <cuda_bf16.h>
#include <math.h>

#define B_   64
#define S_   4096
#define DEC_ 512
#define ENC_ 256

// ---------------- device scratch (allocation-free rule) ----------------
__device__ float2 g_dw[B_ * ENC_];                    // (dpe, Wa) per (b,f)
__device__ float  g_scores[B_ * S_];
__device__ float  g_cpart[8 * B_ * ENC_];
// We^T bf16 hi/lo, per K-chunk of 32, rows padded to 80 B (ldmatrix conflict-free)
__device__ __align__(16) unsigned char g_Bt[2][8][256][80];

// ---------------- smem layout (bytes) ----------------
#define OSTG(buf)    ((unsigned)(buf) * 16384u)                 // fp32 A stage [128][32]
#define OAI(buf, w)  (32768u + (unsigned)(buf) * 20480u + (unsigned)(w) * 10240u) // A bf16 [128][80B]
#define OBI(buf, w)  (73728u + (unsigned)(buf) * 40960u + (unsigned)(w) * 20480u) // B bf16 [256][80B]
#define ODW          155648u                                    // float2[256]
#define ORED         157696u                                    // float[128][9]
#define SMEM_BYTES   162304u

static __device__ __forceinline__ unsigned s2u(const void* p) {
    unsigned a;
    asm("{ .reg .u64 t; cvta.to.shared.u64 t, %1; cvt.u32.u64 %0, t; }" : "=r"(a) : "l"(p));
    return a;
}
static __device__ __forceinline__ void cp16(unsigned dst, const void* src) {
    asm volatile("cp.async.cg.shared.global [%0], [%1], 16;" :: "r"(dst), "l"(src));
}
#define CP_COMMIT() asm volatile("cp.async.commit_group;" ::: "memory")
#define CP_WAIT0()  asm volatile("cp.async.wait_group 0;" ::: "memory")

#define LDM4(r, addr) \
    asm volatile("ldmatrix.sync.aligned.m8n8.x4.shared.b16 {%0,%1,%2,%3}, [%4];" \
        : "=r"((r)[0]), "=r"((r)[1]), "=r"((r)[2]), "=r"((r)[3]) : "r"(addr))

#define MMA(d, a, b0, b1) \
    asm volatile("mma.sync.aligned.m16n8k16.row.col.f32.bf16.bf16.f32 " \
        "{%0,%1,%2,%3}, {%4,%5,%6,%7}, {%8,%9}, {%0,%1,%2,%3};" \
        : "+f"((d)[0]), "+f"((d)[1]), "+f"((d)[2]), "+f"((d)[3]) \
        : "r"((a)[0]), "r"((a)[1]), "r"((a)[2]), "r"((a)[3]), "r"(b0), "r"(b1))

static __device__ __forceinline__ float tanh_fast(float x) {
    float e = __expf(x + x);
    return 1.f - __fdividef(2.f, e + 1.f);
}

// ---------------------------------------------------------------------------
// Prep: We^T -> bf16 hi/lo chunk images, rows padded to 80 B
// ---------------------------------------------------------------------------
__global__ void k_prep(const float* __restrict__ We) {
    int k = blockIdx.x, n = threadIdx.x;
    float v = We[k * 256 + n];
    __nv_bfloat16 h = __float2bfloat16_rn(v);
    __nv_bfloat16 l = __float2bfloat16_rn(v - __bfloat162float(h));
    int ch = k >> 5, kc = k & 31;
    *(__nv_bfloat16*)&g_Bt[0][ch][n][kc * 2] = h;
    *(__nv_bfloat16*)&g_Bt[1][ch][n][kc * 2] = l;
}

// ---------------------------------------------------------------------------
// dpe[b,f] = dh[b,:]@Wd[:,f] + bd + be, paired with Wa
// ---------------------------------------------------------------------------
__global__ void k_decproj(const float* __restrict__ dh, const float* __restrict__ Wd,
                          const float* __restrict__ bd, const float* __restrict__ be,
                          const float* __restrict__ Wa) {
    int b = blockIdx.x, f = threadIdx.x;
    __shared__ float sdh[DEC_];
    for (int d = f; d < DEC_; d += ENC_) sdh[d] = dh[b * DEC_ + d];
    __syncthreads();
    float acc = bd[f] + be[f];
#pragma unroll 8
    for (int d = 0; d < DEC_; ++d) acc += sdh[d] * Wd[d * ENC_ + f];
    g_dw[b * ENC_ + f] = make_float2(acc, Wa[f]);
}

// ---------------------------------------------------------------------------
// k_scores: bf16x3-split HMMA GEMM (mma.sync) + fused tanh*Wa epilogue
// ---------------------------------------------------------------------------
static __device__ __forceinline__ void load_chunk(unsigned sb, const float* __restrict__ enc,
                                                  int row0, int c) {
    const int tid = threadIdx.x;
    const int buf = c & 1;
#pragma unroll
    for (int i = 0; i < 2; ++i) {                     // A stage: 1024 float4
        int idx = tid + i * 512;
        int r = idx >> 3, seg = idx & 7;
        int unit = (((seg >> 1) ^ (r & 3)) << 1) + (seg & 1);   // 32B-chunk XOR swizzle
        cp16(sb + OSTG(buf) + (unsigned)r * 128u + (unsigned)unit * 16u,
             enc + (size_t)(row0 + r) * 256 + c * 32 + seg * 4);
    }
#pragma unroll
    for (int i = 0; i < 5; ++i) {                     // B images: 2560 x 16B
        int u = tid + i * 512;
        int hl = u / 1280, rem = u - hl * 1280;
        int r = rem / 5, seg = rem - r * 5;
        cp16(sb + OBI(buf, hl) + (unsigned)r * 80u + (unsigned)seg * 16u,
             &g_Bt[hl][c][r][seg * 16]);
    }
    CP_COMMIT();
}

__global__ __launch_bounds__(512, 1)
void k_scores(const float* __restrict__ enc) {
    extern __shared__ __align__(16) unsigned char sm[];
    const unsigned sb = s2u(sm);
    const int tid = threadIdx.x, lane = tid & 31, w = tid >> 5;
    const int rowhalf = w >> 3, colg = w & 7;
    const int row0 = blockIdx.x << 7, b = row0 >> 12;

    load_chunk(sb, enc, row0, 0);
    if (tid < 256) ((float2*)(sm + ODW))[tid] = g_dw[b * 256 + tid];

    float acc[4][4][4];
#pragma unroll
    for (int mi = 0; mi < 4; ++mi)
#pragma unroll
        for (int ni = 0; ni < 4; ++ni)
#pragma unroll
            for (int q = 0; q < 4; ++q) acc[mi][ni][q] = 0.f;

    // ldmatrix lane addressing (fixed per thread)
    const unsigned a_row = (unsigned)(rowhalf * 64 + (lane & 15));
    const unsigned a_koff = ((lane >> 4) & 1) * 16u;
    const unsigned b_row = (unsigned)(colg * 32 + (lane & 7) + ((lane >> 4) & 1) * 8);
    const unsigned b_koff = ((lane >> 3) & 1) * 16u;

#pragma unroll 1
    for (int c = 0; c < 8; ++c) {
        const int buf = c & 1;
        CP_WAIT0();
        __syncthreads();
        // convert fp32 stage -> bf16 hi/lo images (one 8-float slice per thread)
        {
            int r = tid >> 2, ch = tid & 3;
            int pch = ch ^ (r & 3);
            const float4* s4 = (const float4*)(sm + OSTG(buf) + (unsigned)r * 128u +
                                               (unsigned)pch * 32u);
            float4 v0 = s4[0], v1 = s4[1];
            float vf[8] = {v0.x, v0.y, v0.z, v0.w, v1.x, v1.y, v1.z, v1.w};
            unsigned hu[4], lu[4];
#pragma unroll
            for (int q = 0; q < 4; ++q) {
                __nv_bfloat16 h0 = __float2bfloat16_rn(vf[2 * q]);
                __nv_bfloat16 h1 = __float2bfloat16_rn(vf[2 * q + 1]);
                __nv_bfloat162 hp = __halves2bfloat162(h0, h1);
                __nv_bfloat162 lp = __halves2bfloat162(
                    __float2bfloat16_rn(vf[2 * q] - __bfloat162float(h0)),
                    __float2bfloat16_rn(vf[2 * q + 1] - __bfloat162float(h1)));
                hu[q] = *(unsigned*)&hp;
                lu[q] = *(unsigned*)&lp;
            }
            unsigned dsth = sb + OAI(buf, 0) + (unsigned)r * 80u + (unsigned)ch * 16u;
            unsigned dstl = sb + OAI(buf, 1) + (unsigned)r * 80u + (unsigned)ch * 16u;
            asm volatile("st.shared.v4.b32 [%0], {%1,%2,%3,%4};"
                         :: "r"(dsth), "r"(hu[0]), "r"(hu[1]), "r"(hu[2]), "r"(hu[3]));
            asm volatile("st.shared.v4.b32 [%0], {%1,%2,%3,%4};"
                         :: "r"(dstl), "r"(lu[0]), "r"(lu[1]), "r"(lu[2]), "r"(lu[3]));
        }
        __syncthreads();
        if (c < 7) load_chunk(sb, enc, row0, c + 1);  // overlap with MMA below

        const unsigned ah_b = sb + OAI(buf, 0), al_b = sb + OAI(buf, 1);
        const unsigned bh_b = sb + OBI(buf, 0), bl_b = sb + OBI(buf, 1);
#pragma unroll
        for (int ks = 0; ks < 2; ++ks) {
            const unsigned ak = a_koff + ks * 32u, bk = b_koff + ks * 32u;
            unsigned af[4][4], bh[4][2], bl[4][2];
#pragma unroll
            for (int mi = 0; mi < 4; ++mi)
                LDM4(af[mi], ah_b + (a_row + mi * 16u) * 80u + ak);
#pragma unroll
            for (int p = 0; p < 2; ++p) {
                unsigned r4[4];
                LDM4(r4, bh_b + (b_row + p * 16u) * 80u + bk);
                bh[2 * p][0] = r4[0]; bh[2 * p][1] = r4[1];
                bh[2 * p + 1][0] = r4[2]; bh[2 * p + 1][1] = r4[3];
                LDM4(r4, bl_b + (b_row + p * 16u) * 80u + bk);
                bl[2 * p][0] = r4[0]; bl[2 * p][1] = r4[1];
                bl[2 * p + 1][0] = r4[2]; bl[2 * p + 1][1] = r4[3];
            }
#pragma unroll
            for (int mi = 0; mi < 4; ++mi)
#pragma unroll
                for (int ni = 0; ni < 4; ++ni) {
                    MMA(acc[mi][ni], af[mi], bh[ni][0], bh[ni][1]);
                    MMA(acc[mi][ni], af[mi], bl[ni][0], bl[ni][1]);
                }
#pragma unroll
            for (int mi = 0; mi < 4; ++mi)            // reuse af regs for A_lo
                LDM4(af[mi], al_b + (a_row + mi * 16u) * 80u + ak);
#pragma unroll
            for (int mi = 0; mi < 4; ++mi)
#pragma unroll
                for (int ni = 0; ni < 4; ++ni)
                    MMA(acc[mi][ni], af[mi], bh[ni][0], bh[ni][1]);
        }
    }

    // Epilogue: scores partial = sum_cols Wa * tanh(dpe + v)
    const float2* sdw = (const float2*)(sm + ODW);
    float* red = (float*)(sm + ORED);
#pragma unroll
    for (int mi = 0; mi < 4; ++mi) {
        float p0 = 0.f, p1 = 0.f;
#pragma unroll
        for (int ni = 0; ni < 4; ++ni) {
            int cc = colg * 32 + ni * 8 + 2 * (lane & 3);
            float2 w0 = sdw[cc], w1 = sdw[cc + 1];
            p0 += w0.y * tanh_fast(acc[mi][ni][0] + w0.x) +
                  w1.y * tanh_fast(acc[mi][ni][1] + w1.x);
            p1 += w0.y * tanh_fast(acc[mi][ni][2] + w0.x) +
                  w1.y * tanh_fast(acc[mi][ni][3] + w1.x);
        }
        p0 += __shfl_xor_sync(~0u, p0, 1); p0 += __shfl_xor_sync(~0u, p0, 2);
        p1 += __shfl_xor_sync(~0u, p1, 1); p1 += __shfl_xor_sync(~0u, p1, 2);
        if ((lane & 3) == 0) {
            int r = rowhalf * 64 + mi * 16 + (lane >> 2);
            red[r * 9 + colg] = p0;
            red[(r + 8) * 9 + colg] = p1;
        }
    }
    __syncthreads();
    if (tid < 128) {
        float s = 0.f;
#pragma unroll
        for (int j = 0; j < 8; ++j) s += red[tid * 9 + j];
        g_scores[row0 + tid] = s;
    }
}

// ---------------------------------------------------------------------------
// Masked softmax over S per batch
// ---------------------------------------------------------------------------
__global__ void k_softmax(const int* __restrict__ mask, float* __restrict__ attn) {
    const int b = blockIdx.x, t = threadIdx.x;
    const float* sc = g_scores + b * S_;
    const int* mk = mask + b * S_;
    float v[4], mx = -INFINITY;
#pragma unroll
    for (int i = 0; i < 4; ++i) {
        int s = t + i * 1024;
        float x = (mk[s] == 0) ? -1e10f : sc[s];
        v[i] = x; mx = fmaxf(mx, x);
    }
    __shared__ float rb[32];
    for (int o = 16; o; o >>= 1) mx = fmaxf(mx, __shfl_xor_sync(~0u, mx, o));
    if ((t & 31) == 0) rb[t >> 5] = mx;
    __syncthreads();
    if (t < 32) {
        float m2 = rb[t];
        for (int o = 16; o; o >>= 1) m2 = fmaxf(m2, __shfl_xor_sync(~0u, m2, o));
        rb[t] = m2;
    }
    __syncthreads();
    mx = rb[0];
    __syncthreads();
    float e[4], tot = 0.f;
#pragma unroll
    for (int i = 0; i < 4; ++i) { e[i] = expf(v[i] - mx); tot += e[i]; }
    for (int o = 16; o; o >>= 1) tot += __shfl_xor_sync(~0u, tot, o);
    if ((t & 31) == 0) rb[t >> 5] = tot;
    __syncthreads();
    if (t < 32) {
        float s2 = rb[t];
        for (int o = 16; o; o >>= 1) s2 += __shfl_xor_sync(~0u, s2, o);
        rb[t] = s2;
    }
    __syncthreads();
    const float inv = 1.f / rb[0];
#pragma unroll
    for (int i = 0; i < 4; ++i) attn[b * S_ + t + i * 1024] = e[i] * inv;
}

// ---------------------------------------------------------------------------
// Context: split S over 8 segments (512 CTAs) + reduce
// ---------------------------------------------------------------------------
__global__ void k_context(const float* __restrict__ enc, const float* __restrict__ attn) {
    const int seg = blockIdx.x & 7, b = blockIdx.x >> 3, t = threadIdx.x;
    const int c4 = t & 63, sg = t >> 6;
    const float4* e4 = (const float4*)enc + (size_t)b * S_ * 64;
    const float* at = attn + b * S_;
    float4 acc = make_float4(0.f, 0.f, 0.f, 0.f);
    const int s0 = seg * 512;
#pragma unroll 4
    for (int s = s0 + sg; s < s0 + 512; s += 4) {
        float a = at[s];
        float4 e = e4[(size_t)s * 64 + c4];
        acc.x += a * e.x; acc.y += a * e.y; acc.z += a * e.z; acc.w += a * e.w;
    }
    __shared__ float4 sr[4][64];
    sr[sg][c4] = acc;
    __syncthreads();
    if (t < 64) {
        float4 r = sr[0][t];
#pragma unroll
        for (int g = 1; g < 4; ++g) {
            float4 q = sr[g][t];
            r.x += q.x; r.y += q.y; r.z += q.z; r.w += q.w;
        }
        ((float4*)g_cpart)[(b * 8 + seg) * 64 + t] = r;
    }
}
__global__ void k_cred(float* __restrict__ ctx) {
    const int b = blockIdx.x, t = threadIdx.x;
    const float4* p = (const float4*)g_cpart;
    float4 r = make_float4(0.f, 0.f, 0.f, 0.f);
#pragma unroll
    for (int seg = 0; seg < 8; ++seg) {
        float4 q = p[(b * 8 + seg) * 64 + t];
        r.x += q.x; r.y += q.y; r.z += q.z; r.w += q.w;
    }
    ((float4*)ctx)[b * 64 + t] = r;
}

// ---------------------------------------------------------------------------
extern "C" void kernel_launch(void* const* d_in, const int* in_sizes, int n_in,
                              void* d_out, int out_size) {
    const float* dh   = (const float*)d_in[0];
    const float* enc  = (const float*)d_in[1];
    const int*   mask = (const int*)  d_in[2];
    const float* Wd   = (const float*)d_in[3];
    const float* bd   = (const float*)d_in[4];
    const float* We   = (const float*)d_in[5];
    const float* be   = (const float*)d_in[6];
    const float* Wa   = (const float*)d_in[7];
    // d_in[8] = ba: uniform shift on scores, cancels in softmax

    float* out  = (float*)d_out;
    float* ctx  = out;
    float* attn = out + B_ * ENC_;

    cudaFuncSetAttribute(k_scores, cudaFuncAttributeMaxDynamicSharedMemorySize, SMEM_BYTES);

    k_prep<<<256, 256>>>(We);
    k_decproj<<<B_, ENC_>>>(dh, Wd, bd, be, Wa);
    k_scores<<<(B_ * S_) / 128, 512, SMEM_BYTES>>>(enc);
    k_softmax<<<B_, 1024>>>(mask, attn);
    k_context<<<8 * B_, 256>>>(enc, attn);
    k_cred<<<B_, 64>>>(ctx);
}

// round 6
// speedup vs baseline: 2.2053x; 1.0729x over previous
#include <cuda_runtime.h>
#include <cuda_bf16.h>
#include <math.h>

#define B_   64
#define S_   4096
#define DEC_ 512
#define ENC_ 256
#define MT   64                                        // rows per k_scores tile

// ---------------- device scratch (allocation-free rule) ----------------
__device__ float2 g_dw[B_ * ENC_];                    // (dpe, Wa) per (b,f)
__device__ float  g_scores[B_ * S_];
__device__ float  g_cpart[8 * B_ * ENC_];
// We^T bf16 hi/lo, per K-chunk of 32, rows padded to 80 B (ldmatrix conflict-free)
__device__ __align__(16) unsigned char g_Bt[2][8][256][80];

// ---------------- smem layout (bytes), per CTA = 112640 ----------------
#define OBI(buf, w)  ((unsigned)(buf) * 40960u + (unsigned)(w) * 20480u)  // B [256][80]
#define OAI(buf, w)  (81920u + (unsigned)(buf) * 10240u + (unsigned)(w) * 5120u) // A [64][80]
#define OSTG         102400u                           // fp32 stage [64][32] (reused: red)
#define ODW          110592u                           // float2[256]
#define SMEM_BYTES   112640u

static __device__ __forceinline__ unsigned s2u(const void* p) {
    unsigned a;
    asm("{ .reg .u64 t; cvta.to.shared.u64 t, %1; cvt.u32.u64 %0, t; }" : "=r"(a) : "l"(p));
    return a;
}
static __device__ __forceinline__ void cp16(unsigned dst, const void* src) {
    asm volatile("cp.async.cg.shared.global [%0], [%1], 16;" :: "r"(dst), "l"(src));
}
#define CP_COMMIT() asm volatile("cp.async.commit_group;" ::: "memory")
#define CP_WAIT0()  asm volatile("cp.async.wait_group 0;" ::: "memory")

#define LDM4(r, addr) \
    asm volatile("ldmatrix.sync.aligned.m8n8.x4.shared.b16 {%0,%1,%2,%3}, [%4];" \
        : "=r"((r)[0]), "=r"((r)[1]), "=r"((r)[2]), "=r"((r)[3]) : "r"(addr))

#define MMA(d, a, b0, b1) \
    asm volatile("mma.sync.aligned.m16n8k16.row.col.f32.bf16.bf16.f32 " \
        "{%0,%1,%2,%3}, {%4,%5,%6,%7}, {%8,%9}, {%0,%1,%2,%3};" \
        : "+f"((d)[0]), "+f"((d)[1]), "+f"((d)[2]), "+f"((d)[3]) \
        : "r"((a)[0]), "r"((a)[1]), "r"((a)[2]), "r"((a)[3]), "r"(b0), "r"(b1))

static __device__ __forceinline__ float tanh_fast(float x) {
    float e = __expf(x + x);
    return 1.f - __fdividef(2.f, e + 1.f);
}

// ---------------------------------------------------------------------------
// Prep: We^T -> bf16 hi/lo chunk images, rows padded to 80 B
// ---------------------------------------------------------------------------
__global__ void k_prep(const float* __restrict__ We) {
    int k = blockIdx.x, n = threadIdx.x;
    float v = We[k * 256 + n];
    __nv_bfloat16 h = __float2bfloat16_rn(v);
    __nv_bfloat16 l = __float2bfloat16_rn(v - __bfloat162float(h));
    int ch = k >> 5, kc = k & 31;
    *(__nv_bfloat16*)&g_Bt[0][ch][n][kc * 2] = h;
    *(__nv_bfloat16*)&g_Bt[1][ch][n][kc * 2] = l;
}

// ---------------------------------------------------------------------------
// dpe[b,f] = dh[b,:]@Wd[:,f] + bd + be, paired with Wa
// ---------------------------------------------------------------------------
__global__ void k_decproj(const float* __restrict__ dh, const float* __restrict__ Wd,
                          const float* __restrict__ bd, const float* __restrict__ be,
                          const float* __restrict__ Wa) {
    int b = blockIdx.x, f = threadIdx.x;
    __shared__ float sdh[DEC_];
    for (int d = f; d < DEC_; d += ENC_) sdh[d] = dh[b * DEC_ + d];
    __syncthreads();
    float acc = bd[f] + be[f];
#pragma unroll 8
    for (int d = 0; d < DEC_; ++d) acc += sdh[d] * Wd[d * ENC_ + f];
    g_dw[b * ENC_ + f] = make_float2(acc, Wa[f]);
}

// ---------------------------------------------------------------------------
// k_scores: 64x256 tile, 256 threads, 2 CTAs/SM; bf16x3-split HMMA + tanh*Wa
// ---------------------------------------------------------------------------
static __device__ __forceinline__ void load_chunk(unsigned sb, const float* __restrict__ enc,
                                                  int row0, int c) {
    const int tid = threadIdx.x;
    const int buf = c & 1;
#pragma unroll
    for (int i = 0; i < 2; ++i) {                     // A stage: 512 float4 (single buf)
        int idx = tid + i * 256;
        int r = idx >> 3, seg = idx & 7;
        int unit = (((seg >> 1) ^ (r & 3)) << 1) + (seg & 1);
        cp16(sb + OSTG + (unsigned)r * 128u + (unsigned)unit * 16u,
             enc + (size_t)(row0 + r) * 256 + c * 32 + seg * 4);
    }
#pragma unroll
    for (int i = 0; i < 10; ++i) {                    // B images: 2560 x 16B
        int u = tid + i * 256;
        int hl = u / 1280, rem = u - hl * 1280;
        int r = rem / 5, seg = rem - r * 5;
        cp16(sb + OBI(buf, hl) + (unsigned)r * 80u + (unsigned)seg * 16u,
             &g_Bt[hl][c][r][seg * 16]);
    }
    CP_COMMIT();
}

__global__ __launch_bounds__(256, 2)
void k_scores(const float* __restrict__ enc) {
    extern __shared__ __align__(16) unsigned char sm[];
    const unsigned sb = s2u(sm);
    const int tid = threadIdx.x, lane = tid & 31, w = tid >> 5;
    const int wr = w & 1, wc = w >> 1;                // 2 row-groups x 4 col-groups
    const int row0 = blockIdx.x * MT, b = row0 >> 12;

    load_chunk(sb, enc, row0, 0);
    ((float2*)(sm + ODW))[tid] = g_dw[b * 256 + tid];

    float acc[2][8][4];
#pragma unroll
    for (int mi = 0; mi < 2; ++mi)
#pragma unroll
        for (int ni = 0; ni < 8; ++ni)
#pragma unroll
            for (int q = 0; q < 4; ++q) acc[mi][ni][q] = 0.f;

    const unsigned a_row = (unsigned)(wr * 32 + (lane & 15));
    const unsigned a_koff = ((lane >> 4) & 1) * 16u;
    const unsigned b_row = (unsigned)(wc * 64 + (lane & 7) + ((lane >> 4) & 1) * 8);
    const unsigned b_koff = ((lane >> 3) & 1) * 16u;

#pragma unroll 1
    for (int c = 0; c < 8; ++c) {
        const int buf = c & 1;
        CP_WAIT0();
        __syncthreads();
        // convert fp32 stage -> bf16 hi/lo images (8 floats per thread)
        {
            int r = tid >> 2, ch = tid & 3;
            int pch = ch ^ (r & 3);
            const float4* s4 = (const float4*)(sm + OSTG + (unsigned)r * 128u +
                                               (unsigned)pch * 32u);
            float4 v0 = s4[0], v1 = s4[1];
            float vf[8] = {v0.x, v0.y, v0.z, v0.w, v1.x, v1.y, v1.z, v1.w};
            unsigned hu[4], lu[4];
#pragma unroll
            for (int q = 0; q < 4; ++q) {
                __nv_bfloat16 h0 = __float2bfloat16_rn(vf[2 * q]);
                __nv_bfloat16 h1 = __float2bfloat16_rn(vf[2 * q + 1]);
                __nv_bfloat162 hp = __halves2bfloat162(h0, h1);
                __nv_bfloat162 lp = __halves2bfloat162(
                    __float2bfloat16_rn(vf[2 * q] - __bfloat162float(h0)),
                    __float2bfloat16_rn(vf[2 * q + 1] - __bfloat162float(h1)));
                hu[q] = *(unsigned*)&hp;
                lu[q] = *(unsigned*)&lp;
            }
            unsigned dsth = sb + OAI(buf, 0) + (unsigned)r * 80u + (unsigned)ch * 16u;
            unsigned dstl = sb + OAI(buf, 1) + (unsigned)r * 80u + (unsigned)ch * 16u;
            asm volatile("st.shared.v4.b32 [%0], {%1,%2,%3,%4};"
                         :: "r"(dsth), "r"(hu[0]), "r"(hu[1]), "r"(hu[2]), "r"(hu[3]));
            asm volatile("st.shared.v4.b32 [%0], {%1,%2,%3,%4};"
                         :: "r"(dstl), "r"(lu[0]), "r"(lu[1]), "r"(lu[2]), "r"(lu[3]));
        }
        __syncthreads();
        if (c < 7) load_chunk(sb, enc, row0, c + 1);  // overlaps MMA below

        const unsigned ah_b = sb + OAI(buf, 0), al_b = sb + OAI(buf, 1);
        const unsigned bh_b = sb + OBI(buf, 0), bl_b = sb + OBI(buf, 1);
#pragma unroll
        for (int ks = 0; ks < 2; ++ks) {
            const unsigned ak = a_koff + ks * 32u, bk = b_koff + ks * 32u;
            unsigned af[2][4], bh[8][2], bl[8][2];
#pragma unroll
            for (int mi = 0; mi < 2; ++mi)
                LDM4(af[mi], ah_b + (a_row + mi * 16u) * 80u + ak);
#pragma unroll
            for (int p = 0; p < 4; ++p) {
                unsigned r4[4];
                LDM4(r4, bh_b + (b_row + p * 16u) * 80u + bk);
                bh[2 * p][0] = r4[0]; bh[2 * p][1] = r4[1];
                bh[2 * p + 1][0] = r4[2]; bh[2 * p + 1][1] = r4[3];
                LDM4(r4, bl_b + (b_row + p * 16u) * 80u + bk);
                bl[2 * p][0] = r4[0]; bl[2 * p][1] = r4[1];
                bl[2 * p + 1][0] = r4[2]; bl[2 * p + 1][1] = r4[3];
            }
#pragma unroll
            for (int mi = 0; mi < 2; ++mi)
#pragma unroll
                for (int ni = 0; ni < 8; ++ni) {
                    MMA(acc[mi][ni], af[mi], bh[ni][0], bh[ni][1]);
                    MMA(acc[mi][ni], af[mi], bl[ni][0], bl[ni][1]);
                }
#pragma unroll
            for (int mi = 0; mi < 2; ++mi)            // reuse af regs for A_lo
                LDM4(af[mi], al_b + (a_row + mi * 16u) * 80u + ak);
#pragma unroll
            for (int mi = 0; mi < 2; ++mi)
#pragma unroll
                for (int ni = 0; ni < 8; ++ni)
                    MMA(acc[mi][ni], af[mi], bh[ni][0], bh[ni][1]);
        }
    }

    // Epilogue: partial scores = sum_cols Wa * tanh(dpe + v); red reuses stage
    const float2* sdw = (const float2*)(sm + ODW);
    float* red = (float*)(sm + OSTG);                 // [64][5] padded
#pragma unroll
    for (int mi = 0; mi < 2; ++mi) {
        float p0 = 0.f, p1 = 0.f;
#pragma unroll
        for (int ni = 0; ni < 8; ++ni) {
            int cc = wc * 64 + ni * 8 + 2 * (lane & 3);
            float2 w0 = sdw[cc], w1 = sdw[cc + 1];
            p0 += w0.y * tanh_fast(acc[mi][ni][0] + w0.x) +
                  w1.y * tanh_fast(acc[mi][ni][1] + w1.x);
            p1 += w0.y * tanh_fast(acc[mi][ni][2] + w0.x) +
                  w1.y * tanh_fast(acc[mi][ni][3] + w1.x);
        }
        p0 += __shfl_xor_sync(~0u, p0, 1); p0 += __shfl_xor_sync(~0u, p0, 2);
        p1 += __shfl_xor_sync(~0u, p1, 1); p1 += __shfl_xor_sync(~0u, p1, 2);
        if ((lane & 3) == 0) {
            int r = wr * 32 + mi * 16 + (lane >> 2);
            red[r * 5 + wc] = p0;
            red[(r + 8) * 5 + wc] = p1;
        }
    }
    __syncthreads();
    if (tid < MT) {
        float s = red[tid * 5] + red[tid * 5 + 1] + red[tid * 5 + 2] + red[tid * 5 + 3];
        g_scores[row0 + tid] = s;
    }
}

// ---------------------------------------------------------------------------
// Masked softmax over S per batch
// ---------------------------------------------------------------------------
__global__ void k_softmax(const int* __restrict__ mask, float* __restrict__ attn) {
    const int b = blockIdx.x, t = threadIdx.x;
    const float* sc = g_scores + b * S_;
    const int* mk = mask + b * S_;
    float v[4], mx = -INFINITY;
#pragma unroll
    for (int i = 0; i < 4; ++i) {
        int s = t + i * 1024;
        float x = (mk[s] == 0) ? -1e10f : sc[s];
        v[i] = x; mx = fmaxf(mx, x);
    }
    __shared__ float rb[32];
    for (int o = 16; o; o >>= 1) mx = fmaxf(mx, __shfl_xor_sync(~0u, mx, o));
    if ((t & 31) == 0) rb[t >> 5] = mx;
    __syncthreads();
    if (t < 32) {
        float m2 = rb[t];
        for (int o = 16; o; o >>= 1) m2 = fmaxf(m2, __shfl_xor_sync(~0u, m2, o));
        rb[t] = m2;
    }
    __syncthreads();
    mx = rb[0];
    __syncthreads();
    float e[4], tot = 0.f;
#pragma unroll
    for (int i = 0; i < 4; ++i) { e[i] = expf(v[i] - mx); tot += e[i]; }
    for (int o = 16; o; o >>= 1) tot += __shfl_xor_sync(~0u, tot, o);
    if ((t & 31) == 0) rb[t >> 5] = tot;
    __syncthreads();
    if (t < 32) {
        float s2 = rb[t];
        for (int o = 16; o; o >>= 1) s2 += __shfl_xor_sync(~0u, s2, o);
        rb[t] = s2;
    }
    __syncthreads();
    const float inv = 1.f / rb[0];
#pragma unroll
    for (int i = 0; i < 4; ++i) attn[b * S_ + t + i * 1024] = e[i] * inv;
}

// ---------------------------------------------------------------------------
// Context: split S over 8 segments (512 CTAs) + reduce
// ---------------------------------------------------------------------------
__global__ void k_context(const float* __restrict__ enc, const float* __restrict__ attn) {
    const int seg = blockIdx.x & 7, b = blockIdx.x >> 3, t = threadIdx.x;
    const int c4 = t & 63, sg = t >> 6;
    const float4* e4 = (const float4*)enc + (size_t)b * S_ * 64;
    const float* at = attn + b * S_;
    float4 acc = make_float4(0.f, 0.f, 0.f, 0.f);
    const int s0 = seg * 512;
#pragma unroll 4
    for (int s = s0 + sg; s < s0 + 512; s += 4) {
        float a = at[s];
        float4 e = e4[(size_t)s * 64 + c4];
        acc.x += a * e.x; acc.y += a * e.y; acc.z += a * e.z; acc.w += a * e.w;
    }
    __shared__ float4 sr[4][64];
    sr[sg][c4] = acc;
    __syncthreads();
    if (t < 64) {
        float4 r = sr[0][t];
#pragma unroll
        for (int g = 1; g < 4; ++g) {
            float4 q = sr[g][t];
            r.x += q.x; r.y += q.y; r.z += q.z; r.w += q.w;
        }
        ((float4*)g_cpart)[(b * 8 + seg) * 64 + t] = r;
    }
}
__global__ void k_cred(float* __restrict__ ctx) {
    const int b = blockIdx.x, t = threadIdx.x;
    const float4* p = (const float4*)g_cpart;
    float4 r = make_float4(0.f, 0.f, 0.f, 0.f);
#pragma unroll
    for (int seg = 0; seg < 8; ++seg) {
        float4 q = p[(b * 8 + seg) * 64 + t];
        r.x += q.x; r.y += q.y; r.z += q.z; r.w += q.w;
    }
    ((float4*)ctx)[b * 64 + t] = r;
}

// ---------------------------------------------------------------------------
extern "C" void kernel_launch(void* const* d_in, const int* in_sizes, int n_in,
                              void* d_out, int out_size) {
    const float* dh   = (const float*)d_in[0];
    const float* enc  = (const float*)d_in[1];
    const int*   mask = (const int*)  d_in[2];
    const float* Wd   = (const float*)d_in[3];
    const float* bd   = (const float*)d_in[4];
    const float* We   = (const float*)d_in[5];
    const float* be   = (const float*)d_in[6];
    const float* Wa   = (const float*)d_in[7];
    // d_in[8] = ba: uniform shift on scores, cancels in softmax

    float* out  = (float*)d_out;
    float* ctx  = out;
    float* attn = out + B_ * ENC_;

    cudaFuncSetAttribute(k_scores, cudaFuncAttributeMaxDynamicSharedMemorySize, SMEM_BYTES);

    k_prep<<<256, 256>>>(We);
    k_decproj<<<B_, ENC_>>>(dh, Wd, bd, be, Wa);
    k_scores<<<(B_ * S_) / MT, 256, SMEM_BYTES>>>(enc);
    k_softmax<<<B_, 1024>>>(mask, attn);
    k_context<<<8 * B_, 256>>>(enc, attn);
    k_cred<<<B_, 64>>>(ctx);
}